// round 7
// baseline (speedup 1.0000x reference)
#include <cuda_runtime.h>
#include <cuda_bf16.h>

// SegmentalEmotion: per-sample sliding-window segment means (2-kernel).
// H: [B, T, D] fp32, lengths_sec: [B] fp32.
// Output: S_pad [B, maxS, D] fp32 (+ mask [B, maxS] fp32 appended, auto-detect).
//
// Reference plan (numpy fp64):
//   dur = max(len, 0.001); fps = T/dur
//   win = max(1, rint(fps)); hop = max(1, rint(fps*0.5))
//   n = (T >= win) ? (T-win)/hop + 1 : 0 ; n==0 -> fallback full-T mean
//
// Plan computed per-THREAD in exact integer arithmetic (~40 ALU ops; no fp64,
// no shared memory, no __syncthreads — fp64 per-block cost +4-6us in R4/R5,
// and the thread-0+barrier preamble serialized short blocks in R6):
//   len = m * 2^(e-24)  (frexpf; m = 24-bit int, exact)
//   rint(1500/len) decided by  3000*2^(24-e) <=> (2k+/-1)*m  (int64, exact),
//   round-half-to-even on ties; fp32 divide seeds the candidate k.
//
// Phase 1 (piece_sum): hop-chunks split into <=4 pieces, plen rounded up to
//   a multiple of 8 (no scalar tail except last piece); reads H once.
// Phase 2 (seg_out): 1 segment/block; window s = chunk s + chunk s+1
//   (+/- <=1 edge frame), scale 1/win, write output + mask.

#define T_FRAMES 1500
#define D_DIM    768
#define D_VEC    (D_DIM / 4)   // 192 float4 lanes
#define NTHREADS 192
#define MAX_B    32
#define MAX_NHOP 60            // ceil(1500/25)
#define MAX_NP   4
#define PG       80            // >= max nhop*np
#define PIECE_TGT 38           // target frames per piece

// piece sums: P[b, j, p, :]
__device__ float g_P[(size_t)MAX_B * MAX_NHOP * MAX_NP * D_DIM];

struct Plan { int win, hop, n_eff, nhop, np, plen, fallback; };

// rint(num/len) via exact int64 comparisons. lhs = 2*num * 2^(24-e),
// m = 24-bit mantissa of len, k = fp32 candidate (within +-1 of truth).
__device__ __forceinline__ int rint_ratio_exact(long long lhs, long long m, int k)
{
    while (lhs > (2LL * k + 1) * m) ++k;   // x > k+0.5
    while (lhs < (2LL * k - 1) * m) --k;   // x < k-0.5
    if (lhs == (2LL * k + 1) * m) return k + (k & 1);  // tie at k+0.5 -> even
    if (lhs == (2LL * k - 1) * m) return k - (k & 1);  // tie at k-0.5 -> even
    return k;
}

// Integer-exact plan; cheap enough for every thread.
__device__ __forceinline__ Plan compute_plan(float len)
{
    Plan p;
    int win, hop;
    long long n;
    if (len >= 1.0f && len < 1024.0f) {
        int e;
        float mf = frexpf(len, &e);                    // len = mf*2^e
        long long m = (long long)(mf * 16777216.0f);   // mf*2^24, exact
        const int sh = 24 - e;                         // in [14, 23]
        win = rint_ratio_exact(3000LL << sh, m, (int)lrintf(1500.0f / len));
        hop = rint_ratio_exact(1500LL << sh, m, (int)lrintf(750.0f / len));
        if (win < 1) win = 1;
        if (hop < 1) hop = 1;
        n = (T_FRAMES >= win) ? (long long)(T_FRAMES - win) / hop + 1 : 0;
    } else {
        // exact fp64 replica (never taken for len in [5,30))
        double dur = fmax((double)len, 0.001);
        double fps = (double)T_FRAMES / dur;
        long long w64 = llrint(fps);       if (w64 < 1) w64 = 1;
        long long h64 = llrint(fps * 0.5); if (h64 < 1) h64 = 1;
        n = ((long long)T_FRAMES >= w64)
                ? ((long long)T_FRAMES - w64) / h64 + 1 : 0;
        if (w64 > T_FRAMES + 1) w64 = T_FRAMES + 1;
        if (h64 > T_FRAMES) h64 = T_FRAMES;
        win = (int)w64;
        hop = (int)h64;
    }
    p.fallback = (n == 0);
    p.win   = win;
    p.hop   = hop;
    p.n_eff = (int)(p.fallback ? 1 : n);
    p.nhop  = (T_FRAMES + hop - 1) / hop;
    int np = (hop + PIECE_TGT - 1) / PIECE_TGT;
    if (np > MAX_NP) np = MAX_NP;
    p.np   = np;
    int plen = (hop + np - 1) / np;
    p.plen = (plen + 7) & ~7;              // multiple of 8: no scalar tail
    return p;
}

// ---------- Phase 1: piece sums, reads H exactly once ----------
__global__ __launch_bounds__(NTHREADS)
void piece_sum_kernel(const float* __restrict__ H,
                      const float* __restrict__ lens)
{
    const int b   = blockIdx.y;
    const int tid = threadIdx.x;

    const Plan sp = compute_plan(__ldg(&lens[b]));

    const int np      = sp.np;
    const int hop     = sp.hop;
    const int plen    = sp.plen;
    const int npieces = sp.nhop * np;

    const float4* __restrict__ Hb =
        (const float4*)H + (size_t)b * T_FRAMES * D_VEC + tid;

    for (int m = blockIdx.x; m < npieces; m += PG) {
        const int j = m / np;
        const int p = m - j * np;

        int t0 = j * hop + p * plen;
        int chunk_end = j * hop + hop;
        if (chunk_end > T_FRAMES) chunk_end = T_FRAMES;
        int t1 = t0 + plen;
        if (t1 > chunk_end) t1 = chunk_end;
        if (t0 > chunk_end) t0 = chunk_end;   // piece fully past chunk: empty

        float4 acc = make_float4(0.f, 0.f, 0.f, 0.f);
        int t = t0;
        for (; t + 8 <= t1; t += 8) {
            float4 v0 = __ldcs(&Hb[(t + 0) * D_VEC]);
            float4 v1 = __ldcs(&Hb[(t + 1) * D_VEC]);
            float4 v2 = __ldcs(&Hb[(t + 2) * D_VEC]);
            float4 v3 = __ldcs(&Hb[(t + 3) * D_VEC]);
            float4 v4 = __ldcs(&Hb[(t + 4) * D_VEC]);
            float4 v5 = __ldcs(&Hb[(t + 5) * D_VEC]);
            float4 v6 = __ldcs(&Hb[(t + 6) * D_VEC]);
            float4 v7 = __ldcs(&Hb[(t + 7) * D_VEC]);
            acc.x += v0.x + v1.x + v2.x + v3.x + v4.x + v5.x + v6.x + v7.x;
            acc.y += v0.y + v1.y + v2.y + v3.y + v4.y + v5.y + v6.y + v7.y;
            acc.z += v0.z + v1.z + v2.z + v3.z + v4.z + v5.z + v6.z + v7.z;
            acc.w += v0.w + v1.w + v2.w + v3.w + v4.w + v5.w + v6.w + v7.w;
        }
        for (; t < t1; ++t) {                 // only the last piece of a chunk
            float4 v = __ldcs(&Hb[t * D_VEC]);
            acc.x += v.x; acc.y += v.y; acc.z += v.z; acc.w += v.w;
        }

        ((float4*)g_P)[(((size_t)b * MAX_NHOP + j) * MAX_NP + p) * D_VEC + tid] = acc;
    }
}

// ---------- Phase 2: one segment per block ----------
__global__ __launch_bounds__(NTHREADS)
void seg_out_kernel(const float* __restrict__ H,
                    const float* __restrict__ lens,
                    float* __restrict__ S,      // [B, maxS, D]
                    float* __restrict__ Mout,   // [B, maxS] or nullptr
                    int maxS)
{
    const int s   = blockIdx.x;
    const int b   = blockIdx.y;
    const int tid = threadIdx.x;

    const Plan sp = compute_plan(__ldg(&lens[b]));

    float4* outRow = (float4*)(S + ((size_t)b * maxS + s) * D_DIM);

    if (s >= sp.n_eff) {
        outRow[tid] = make_float4(0.f, 0.f, 0.f, 0.f);
        if (Mout != nullptr && tid == 0)
            Mout[(size_t)b * maxS + s] = 0.f;
        return;
    }

    const int win  = sp.win;
    const int hop  = sp.hop;
    const int nhop = sp.nhop;
    const int np   = sp.np;

    const float4* __restrict__ Pb =
        (const float4*)g_P + (size_t)b * MAX_NHOP * MAX_NP * D_VEC + tid;
    const float4* __restrict__ Hb =
        (const float4*)H + (size_t)b * T_FRAMES * D_VEC + tid;

    float4 acc = make_float4(0.f, 0.f, 0.f, 0.f);
    int cnt;

    if (sp.fallback) {
        for (int j = 0; j < nhop; ++j)
            for (int pp = 0; pp < np; ++pp) {
                float4 v = Pb[((size_t)j * MAX_NP + pp) * D_VEC];
                acc.x += v.x; acc.y += v.y; acc.z += v.z; acc.w += v.w;
            }
        cnt = T_FRAMES;
    } else {
        const int start = s * hop;
        const int end   = start + win;          // <= T for s < n
        const bool have2 = (s + 1) < nhop;

        // issue all piece loads (<=8 independent LDG.128), then reduce
        float4 vbuf[2 * MAX_NP];
        #pragma unroll
        for (int pp = 0; pp < MAX_NP; ++pp)
            vbuf[pp] = (pp < np)
                ? Pb[((size_t)s * MAX_NP + pp) * D_VEC]
                : make_float4(0.f, 0.f, 0.f, 0.f);
        #pragma unroll
        for (int pp = 0; pp < MAX_NP; ++pp)
            vbuf[MAX_NP + pp] = (have2 && pp < np)
                ? Pb[((size_t)(s + 1) * MAX_NP + pp) * D_VEC]
                : make_float4(0.f, 0.f, 0.f, 0.f);
        #pragma unroll
        for (int k = 0; k < 2 * MAX_NP; ++k) {
            acc.x += vbuf[k].x; acc.y += vbuf[k].y;
            acc.z += vbuf[k].z; acc.w += vbuf[k].w;
        }

        int cov_end = start + (have2 ? 2 : 1) * hop;
        if (cov_end > T_FRAMES) cov_end = T_FRAMES;

        for (int t = cov_end; t < end; ++t) {   // add missing (<=1)
            float4 v = Hb[t * D_VEC];
            acc.x += v.x; acc.y += v.y; acc.z += v.z; acc.w += v.w;
        }
        for (int t = end; t < cov_end; ++t) {   // subtract excess (<=1)
            float4 v = Hb[t * D_VEC];
            acc.x -= v.x; acc.y -= v.y; acc.z -= v.z; acc.w -= v.w;
        }
        cnt = win > 0 ? win : 1;
    }

    const float inv = 1.0f / (float)cnt;
    outRow[tid] = make_float4(acc.x * inv, acc.y * inv, acc.z * inv, acc.w * inv);
    if (Mout != nullptr && tid == 0)
        Mout[(size_t)b * maxS + s] = 1.f;
}

extern "C" void kernel_launch(void* const* d_in, const int* in_sizes, int n_in,
                              void* d_out, int out_size)
{
    const float* H    = (const float*)d_in[0];
    const float* lens = (const float*)d_in[1];
    float* out        = (float*)d_out;

    const int B = in_sizes[1];  // 32

    // Infer maxS and mask presence from out_size (768, 769 coprime; maxS << 768).
    int maxS;
    bool has_mask;
    if (out_size % (B * (D_DIM + 1)) == 0) {
        maxS = out_size / (B * (D_DIM + 1));
        has_mask = true;
    } else {
        maxS = out_size / (B * D_DIM);
        has_mask = false;
    }

    float* Mout = has_mask ? (out + (size_t)B * maxS * D_DIM) : nullptr;

    dim3 grid1(PG, B);
    piece_sum_kernel<<<grid1, NTHREADS>>>(H, lens);

    dim3 grid2(maxS, B);
    seg_out_kernel<<<grid2, NTHREADS>>>(H, lens, out, Mout, maxS);
}